// round 2
// baseline (speedup 1.0000x reference)
#include <cuda_runtime.h>

#define NN 50000
#define EE 800000
#define EP (EE + NN)
#define HH 4
#define CC 32
#define HC 128
#define EDIM 8
#define NRELS 16
#define NLAYERS 3
#define HID 100

// ---------- scratch (device globals: no allocation allowed) ----------
__device__ float g_h[NN * HC];          // projected features per layer
__device__ float g_xA[NN * HC];         // ping
__device__ float g_xB[NN * HC];         // pong
__device__ float g_ssrc[NN * HH];
__device__ float g_sdst[NN * HH];
__device__ int   g_rowstart[NN + 1];
__device__ int   g_counts[NN];
__device__ int   g_cursor[NN];
__device__ int2  g_edges[EP];           // (src, type) sorted by dst
__device__ float g_serel[NLAYERS * (NRELS + 1) * HH];
__device__ float g_w0sum[HC];
__device__ int   g_hist[NRELS];
__device__ float g_h1[NN * HID];

// ---------- build: counts + type histogram ----------
__global__ void k_init() {
    int i = blockIdx.x * blockDim.x + threadIdx.x;
    if (i < NN) g_counts[i] = 1;          // self-loop
    if (i < NRELS) g_hist[i] = 0;
}

__global__ void k_histcount(const int* __restrict__ ei, const int* __restrict__ et) {
    __shared__ int sh[NRELS];
    if (threadIdx.x < NRELS) sh[threadIdx.x] = 0;
    __syncthreads();
    int i = blockIdx.x * blockDim.x + threadIdx.x;
    if (i < EE) {
        atomicAdd(&g_counts[ei[EE + i]], 1);
        atomicAdd(&sh[et[i]], 1);
    }
    __syncthreads();
    if (threadIdx.x < NRELS) atomicAdd(&g_hist[threadIdx.x], sh[threadIdx.x]);
}

// ---------- exclusive scan (1 block, hierarchical) ----------
__global__ void k_scan() {
    __shared__ int ss[1024];
    const int CH = (NN + 1023) / 1024;    // 49
    int t = threadIdx.x;
    int beg = t * CH;
    int end = min(beg + CH, NN);
    int s = 0;
    for (int i = beg; i < end; i++) s += g_counts[i];
    ss[t] = s;
    __syncthreads();
    for (int off = 1; off < 1024; off <<= 1) {
        int v = 0;
        if (t >= off) v = ss[t - off];
        __syncthreads();
        ss[t] += v;
        __syncthreads();
    }
    int run = (t == 0) ? 0 : ss[t - 1];
    for (int i = beg; i < end; i++) {
        g_rowstart[i] = run;
        g_cursor[i]   = run;
        run += g_counts[i];
    }
    if (t == 0) g_rowstart[NN] = EP;
}

// ---------- scatter edges into dst-CSR ----------
__global__ void k_scatter(const int* __restrict__ ei, const int* __restrict__ et) {
    int i = blockIdx.x * blockDim.x + threadIdx.x;
    if (i < EE) {
        int d = ei[EE + i];
        int p = atomicAdd(&g_cursor[d], 1);
        g_edges[p] = make_int2(ei[i], et[i]);
    } else if (i < EP) {
        int n = i - EE;
        int p = atomicAdd(&g_cursor[n], 1);
        g_edges[p] = make_int2(n, NRELS);           // self-loop sentinel
    }
}

// ---------- tiny precompute: w0sum + per-relation edge scores ----------
__global__ void k_pre(const float* __restrict__ W0, const float* __restrict__ Wedge,
                      const float* __restrict__ attE, const float* __restrict__ eemb) {
    int t = threadIdx.x;
    if (t < HC) {
        float s = 0.f;
        for (int c = 0; c < CC; c++) s += W0[c * HC + t];
        g_w0sum[t] = s;
    }
    if (t < NLAYERS * (NRELS + 1) * HH) {
        int l = t / ((NRELS + 1) * HH);
        int rem = t % ((NRELS + 1) * HH);
        int r = rem / HH;
        int h = rem % HH;
        float s = 0.f;
        for (int d = 0; d < EDIM; d++) {
            float u = 0.f;
            for (int c = 0; c < CC; c++)
                u += Wedge[(l * EDIM + d) * HC + h * CC + c] * attE[l * HC + h * CC + c];
            float ea;
            if (r < NRELS) {
                ea = eemb[r * EDIM + d];
            } else {
                float f = 0.f;
                for (int rr = 0; rr < NRELS; rr++)
                    f += (float)g_hist[rr] * eemb[rr * EDIM + d];
                ea = f / (float)EE;
            }
            s += ea * u;
        }
        g_serel[t] = s;
    }
}

// ---------- layer-0 projection: rank-1 ----------
__global__ void k_h0(const float* __restrict__ x) {
    int i = blockIdx.x * blockDim.x + threadIdx.x;      // NN*32 float4s
    if (i >= NN * 32) return;
    int n = i >> 5, q = i & 31;
    float xv = x[n];
    float4 w = ((const float4*)g_w0sum)[q];
    ((float4*)g_h)[i] = make_float4(xv * w.x, xv * w.y, xv * w.z, xv * w.w);
}

// ---------- s_src / s_dst: warp per node ----------
__global__ void k_sdot(const float* __restrict__ asrc, const float* __restrict__ adst) {
    __shared__ float sa[HC], sd[HC];
    int t = threadIdx.x;
    if (t < HC) { sa[t] = asrc[t]; sd[t] = adst[t]; }
    __syncthreads();
    int warp = t >> 5, lane = t & 31;
    int n = blockIdx.x * 8 + warp;
    if (n >= NN) return;
    float4 hv = ((const float4*)g_h)[n * 32 + lane];
    float4 a = ((const float4*)sa)[lane];
    float4 d = ((const float4*)sd)[lane];
    float ps = hv.x * a.x + hv.y * a.y + hv.z * a.z + hv.w * a.w;
    float pd = hv.x * d.x + hv.y * d.y + hv.z * d.z + hv.w * d.w;
    // reduce within each 8-lane (per-head) group
    for (int off = 4; off; off >>= 1) {
        ps += __shfl_xor_sync(0xffffffffu, ps, off);
        pd += __shfl_xor_sync(0xffffffffu, pd, off);
    }
    if ((lane & 7) == 0) {
        int h = lane >> 3;
        g_ssrc[n * HH + h] = ps;
        g_sdst[n * HH + h] = pd;
    }
}

// ---------- aggregation: thread per (dst, head), online softmax ----------
__global__ void __launch_bounds__(128) k_agg(const float* __restrict__ bias,
                                             const float* __restrict__ xprev,
                                             float* __restrict__ xout, int layer) {
    __shared__ float sser[(NRELS + 1) * HH];
    __shared__ float sb[HC];
    int t = threadIdx.x;
    if (t < (NRELS + 1) * HH) sser[t] = g_serel[layer * (NRELS + 1) * HH + t];
    if (t < HC) sb[t] = bias[t];
    __syncthreads();
    int n = blockIdx.x * 32 + (t >> 2);
    int hd = t & 3;
    if (n >= NN) return;
    int beg = g_rowstart[n], end = g_rowstart[n + 1];
    float sdv = g_sdst[n * HH + hd];
    float m = -3.0e38f, dsum = 0.f;
    float acc[CC];
#pragma unroll
    for (int c = 0; c < CC; c++) acc[c] = 0.f;
    for (int e = beg; e < end; e++) {
        int2 ed = g_edges[e];
        float a = g_ssrc[ed.x * HH + hd] + sdv + sser[ed.y * HH + hd];
        a = (a > 0.f) ? a : 0.2f * a;                  // leaky_relu
        float w;
        if (a > m) {
            float sc = __expf(m - a);                  // exp(-inf)=0 on first edge
            dsum *= sc;
#pragma unroll
            for (int c = 0; c < CC; c++) acc[c] *= sc;
            m = a;
            w = 1.f;
        } else {
            w = __expf(a - m);
        }
        dsum += w;
        const float4* hp = (const float4*)(g_h + ed.x * HC + hd * CC);
#pragma unroll
        for (int i = 0; i < 8; i++) {
            float4 v = hp[i];
            acc[4 * i + 0] += w * v.x;
            acc[4 * i + 1] += w * v.y;
            acc[4 * i + 2] += w * v.z;
            acc[4 * i + 3] += w * v.w;
        }
    }
    float inv = 1.f / (dsum + 1e-16f);
    int base = n * HC + hd * CC;
#pragma unroll
    for (int i = 0; i < 8; i++) {
        float4 o;
        float* pa = &acc[4 * i];
        o.x = pa[0] * inv + sb[hd * CC + 4 * i + 0];
        o.y = pa[1] * inv + sb[hd * CC + 4 * i + 1];
        o.z = pa[2] * inv + sb[hd * CC + 4 * i + 2];
        o.w = pa[3] * inv + sb[hd * CC + 4 * i + 3];
        if (layer > 0) {
            float4 xp = *(const float4*)(xprev + base + 4 * i);
            o.x += xp.x; o.y += xp.y; o.z += xp.z; o.w += xp.w;
        }
        o.x = fmaxf(o.x, 0.f); o.y = fmaxf(o.y, 0.f);
        o.z = fmaxf(o.z, 0.f); o.w = fmaxf(o.w, 0.f);
        *(float4*)(xout + base + 4 * i) = o;
    }
}

// ---------- tiled SGEMM: C[M,NC] = A[M,128] * B[128,NC] (+bias, relu) ----------
__global__ void __launch_bounds__(256) k_gemm(const float* __restrict__ A,
                                              const float* __restrict__ B,
                                              float* __restrict__ Co,
                                              int M, int NC, int ldb, int ldc,
                                              const float* __restrict__ bias, int dorelu) {
    __shared__ float As[16][HC];
    __shared__ float Bs[16][HC];
    int t = threadIdx.x;
    int tx = t & 15, ty = t >> 4;
    int row0 = blockIdx.x * 128;
    float acc[8][8];
#pragma unroll
    for (int i = 0; i < 8; i++)
#pragma unroll
        for (int j = 0; j < 8; j++) acc[i][j] = 0.f;

    for (int kc = 0; kc < 128; kc += 16) {
#pragma unroll
        for (int i = 0; i < 2; i++) {
            int f = t * 2 + i;          // 0..511
            int r = f >> 2;
            int kq = (f & 3) << 2;
            float4 v = make_float4(0, 0, 0, 0);
            int gr = row0 + r;
            if (gr < M) v = *(const float4*)(A + gr * 128 + kc + kq);
            As[kq + 0][r] = v.x; As[kq + 1][r] = v.y;
            As[kq + 2][r] = v.z; As[kq + 3][r] = v.w;
        }
#pragma unroll
        for (int i = 0; i < 2; i++) {
            int f = t * 2 + i;
            int k = f >> 5;
            int cq = (f & 31) << 2;
            float4 v = make_float4(0, 0, 0, 0);
            if (cq < NC) v = *(const float4*)(B + (kc + k) * ldb + cq);
            Bs[k][cq + 0] = v.x; Bs[k][cq + 1] = v.y;
            Bs[k][cq + 2] = v.z; Bs[k][cq + 3] = v.w;
        }
        __syncthreads();
#pragma unroll
        for (int k = 0; k < 16; k++) {
            float av[8], bv[8];
#pragma unroll
            for (int i = 0; i < 8; i++) av[i] = As[k][ty * 8 + i];
#pragma unroll
            for (int j = 0; j < 8; j++) bv[j] = Bs[k][tx * 8 + j];
#pragma unroll
            for (int i = 0; i < 8; i++)
#pragma unroll
                for (int j = 0; j < 8; j++) acc[i][j] += av[i] * bv[j];
        }
        __syncthreads();
    }
#pragma unroll
    for (int i = 0; i < 8; i++) {
        int gr = row0 + ty * 8 + i;
        if (gr >= M) continue;
#pragma unroll
        for (int j = 0; j < 8; j++) {
            int gc = tx * 8 + j;
            if (gc >= NC) continue;
            float v = acc[i][j];
            if (bias) v += bias[gc];
            if (dorelu) v = fmaxf(v, 0.f);
            Co[gr * ldc + gc] = v;
        }
    }
}

// ---------- final: sigmoid(h1 @ W2 + b2), warp per node ----------
__global__ void k_out(const float* __restrict__ W2, const float* __restrict__ b2,
                      float* __restrict__ out) {
    __shared__ float sw[HID];
    int t = threadIdx.x;
    if (t < HID) sw[t] = W2[t];
    __syncthreads();
    int warp = t >> 5, lane = t & 31;
    int n = blockIdx.x * 8 + warp;
    if (n >= NN) return;
    const float* hp = g_h1 + n * HID;
    float s = hp[lane] * sw[lane] + hp[lane + 32] * sw[lane + 32] + hp[lane + 64] * sw[lane + 64];
    if (lane < 4) s += hp[lane + 96] * sw[lane + 96];
    for (int off = 16; off; off >>= 1) s += __shfl_xor_sync(0xffffffffu, s, off);
    if (lane == 0) out[n] = 1.f / (1.f + __expf(-(s + b2[0])));
}

// ---------- host ----------
extern "C" void kernel_launch(void* const* d_in, const int* in_sizes, int n_in,
                              void* d_out, int out_size) {
    const float* x     = (const float*)d_in[0];
    const int*   ei    = (const int*)d_in[1];
    const int*   et    = (const int*)d_in[2];
    const float* eemb  = (const float*)d_in[3];
    const float* W0    = (const float*)d_in[4];
    const float* W1    = (const float*)d_in[5];
    const float* W2    = (const float*)d_in[6];
    const float* attS  = (const float*)d_in[7];
    const float* attD  = (const float*)d_in[8];
    const float* attE  = (const float*)d_in[9];
    const float* Wedge = (const float*)d_in[10];
    const float* bias  = (const float*)d_in[11];
    const float* mW1   = (const float*)d_in[12];
    const float* mb1   = (const float*)d_in[13];
    const float* mW2   = (const float*)d_in[14];
    const float* mb2   = (const float*)d_in[15];
    float* out = (float*)d_out;

    float *ph, *pxA, *pxB, *ph1;
    cudaGetSymbolAddress((void**)&ph, g_h);
    cudaGetSymbolAddress((void**)&pxA, g_xA);
    cudaGetSymbolAddress((void**)&pxB, g_xB);
    cudaGetSymbolAddress((void**)&ph1, g_h1);

    // graph build (reused by all 3 layers)
    k_init<<<(NN + 255) / 256, 256>>>();
    k_histcount<<<(EE + 255) / 256, 256>>>(ei, et);
    k_scan<<<1, 1024>>>();
    k_scatter<<<(EP + 255) / 256, 256>>>(ei, et);
    k_pre<<<1, 256>>>(W0, Wedge, attE, eemb);

    int gAgg = (NN + 31) / 32;
    int gSd  = (NN + 7) / 8;
    int gGm  = (NN + 127) / 128;

    // layer 0 (rank-1 projection, no residual)
    k_h0<<<(NN * 32 + 255) / 256, 256>>>(x);
    k_sdot<<<gSd, 256>>>(attS + 0 * HC, attD + 0 * HC);
    k_agg<<<gAgg, 128>>>(bias + 0 * HC, nullptr, pxA, 0);

    // layer 1
    k_gemm<<<gGm, 256>>>(pxA, W1, ph, NN, HC, HC, HC, nullptr, 0);
    k_sdot<<<gSd, 256>>>(attS + 1 * HC, attD + 1 * HC);
    k_agg<<<gAgg, 128>>>(bias + 1 * HC, pxA, pxB, 1);

    // layer 2
    k_gemm<<<gGm, 256>>>(pxB, W2, ph, NN, HC, HC, HC, nullptr, 0);
    k_sdot<<<gSd, 256>>>(attS + 2 * HC, attD + 2 * HC);
    k_agg<<<gAgg, 128>>>(bias + 2 * HC, pxB, pxA, 2);

    // MLP head
    k_gemm<<<gGm, 256>>>(pxA, mW1, ph1, NN, HID, HID, HID, mb1, 1);
    k_out<<<gSd, 256>>>(mW2, mb2, out);
}

// round 3
// speedup vs baseline: 1.5798x; 1.5798x over previous
#include <cuda_runtime.h>

#define NN 50000
#define EE 800000
#define EP (EE + NN)
#define HH 4
#define CC 32
#define HC 128
#define EDIM 8
#define NRELS 16
#define NLAYERS 3
#define HID 100

typedef unsigned long long ull;

// ---------- scratch (device globals: no allocation allowed) ----------
__device__ float g_h[NN * HC];          // projected features per layer
__device__ float g_xA[NN * HC];         // ping
__device__ float g_xB[NN * HC];         // pong
__device__ float g_ssrc[NN * HH];
__device__ float g_sdst[NN * HH];
__device__ int   g_rowstart[NN + 1];
__device__ int   g_counts[NN];
__device__ int   g_cursor[NN];
__device__ unsigned g_edgep[EP];        // src | (type<<16), sorted by dst
__device__ float g_serel[NLAYERS * (NRELS + 1) * HH];
__device__ float g_w0sum[HC];
__device__ float g_k0[8];               // layer0 rank-1 att dots (src 0..3, dst 4..7)
__device__ int   g_hist[NRELS];

// ---------- f32x2 helpers ----------
__device__ __forceinline__ void ffma2(ull &d, ull a, ull b) {
    asm("fma.rn.f32x2 %0, %1, %2, %3;" : "=l"(d) : "l"(a), "l"(b), "l"(d));
}
__device__ __forceinline__ ull pack2(float x, float y) {
    ull r; asm("mov.b64 %0, {%1, %2};" : "=l"(r) : "f"(x), "f"(y)); return r;
}
__device__ __forceinline__ float lo2(ull v) { return __uint_as_float((unsigned)v); }
__device__ __forceinline__ float hi2(ull v) { return __uint_as_float((unsigned)(v >> 32)); }

// ---------- build: counts + type histogram ----------
__global__ void k_init() {
    int i = blockIdx.x * blockDim.x + threadIdx.x;
    if (i < NN) g_counts[i] = 1;          // self-loop
    if (i < NRELS) g_hist[i] = 0;
}

__global__ void k_histcount(const int* __restrict__ ei, const int* __restrict__ et) {
    __shared__ int sh[NRELS];
    if (threadIdx.x < NRELS) sh[threadIdx.x] = 0;
    __syncthreads();
    int i = blockIdx.x * blockDim.x + threadIdx.x;
    if (i < EE) {
        atomicAdd(&g_counts[ei[EE + i]], 1);
        atomicAdd(&sh[et[i]], 1);
    }
    __syncthreads();
    if (threadIdx.x < NRELS) atomicAdd(&g_hist[threadIdx.x], sh[threadIdx.x]);
}

// ---------- exclusive scan (1 block, hierarchical) ----------
__global__ void k_scan() {
    __shared__ int ss[1024];
    const int CH = (NN + 1023) / 1024;
    int t = threadIdx.x;
    int beg = t * CH;
    int end = min(beg + CH, NN);
    int s = 0;
    for (int i = beg; i < end; i++) s += g_counts[i];
    ss[t] = s;
    __syncthreads();
    for (int off = 1; off < 1024; off <<= 1) {
        int v = 0;
        if (t >= off) v = ss[t - off];
        __syncthreads();
        ss[t] += v;
        __syncthreads();
    }
    int run = (t == 0) ? 0 : ss[t - 1];
    for (int i = beg; i < end; i++) {
        g_rowstart[i] = run;
        g_cursor[i]   = run;
        run += g_counts[i];
    }
    if (t == 0) g_rowstart[NN] = EP;
}

// ---------- scatter edges into dst-CSR (packed: src | type<<16) ----------
__global__ void k_scatter(const int* __restrict__ ei, const int* __restrict__ et) {
    int i = blockIdx.x * blockDim.x + threadIdx.x;
    if (i < EE) {
        int d = ei[EE + i];
        int p = atomicAdd(&g_cursor[d], 1);
        g_edgep[p] = (unsigned)ei[i] | ((unsigned)et[i] << 16);
    } else if (i < EP) {
        int n = i - EE;
        int p = atomicAdd(&g_cursor[n], 1);
        g_edgep[p] = (unsigned)n | ((unsigned)NRELS << 16);   // self-loop sentinel
    }
}

// ---------- tiny precompute: w0sum + per-relation edge scores + layer0 att dots ----------
__global__ void k_pre(const float* __restrict__ W0, const float* __restrict__ Wedge,
                      const float* __restrict__ attE, const float* __restrict__ eemb,
                      const float* __restrict__ attS, const float* __restrict__ attD) {
    int t = threadIdx.x;
    if (t < HC) {
        float s = 0.f;
        for (int c = 0; c < CC; c++) s += W0[c * HC + t];
        g_w0sum[t] = s;
    }
    if (t < NLAYERS * (NRELS + 1) * HH) {
        int l = t / ((NRELS + 1) * HH);
        int rem = t % ((NRELS + 1) * HH);
        int r = rem / HH;
        int h = rem % HH;
        float s = 0.f;
        for (int d = 0; d < EDIM; d++) {
            float u = 0.f;
            for (int c = 0; c < CC; c++)
                u += Wedge[(l * EDIM + d) * HC + h * CC + c] * attE[l * HC + h * CC + c];
            float ea;
            if (r < NRELS) {
                ea = eemb[r * EDIM + d];
            } else {
                float f = 0.f;
                for (int rr = 0; rr < NRELS; rr++)
                    f += (float)g_hist[rr] * eemb[rr * EDIM + d];
                ea = f / (float)EE;
            }
            s += ea * u;
        }
        g_serel[t] = s;
    }
    __syncthreads();
    if (t < 8) {                    // layer-0 rank-1 attention dots
        int h = t & 3;
        const float* av = (t < 4) ? attS : attD;   // layer0 slice
        float s = 0.f;
        for (int c = 0; c < CC; c++) s += g_w0sum[h * CC + c] * av[h * CC + c];
        g_k0[t] = s;
    }
}

// ---------- layer-0 projection (rank-1) + fused s_src/s_dst ----------
__global__ void k_h0(const float* __restrict__ x) {
    int i = blockIdx.x * blockDim.x + threadIdx.x;      // NN*32 float4s
    if (i >= NN * 32) return;
    int n = i >> 5, q = i & 31;
    float xv = x[n];
    float4 w = ((const float4*)g_w0sum)[q];
    ((float4*)g_h)[i] = make_float4(xv * w.x, xv * w.y, xv * w.z, xv * w.w);
    if (q < 8) {
        float v = xv * g_k0[q];
        if (q < 4) g_ssrc[n * HH + q] = v;
        else       g_sdst[n * HH + (q - 4)] = v;
    }
}

// ---------- s_src / s_dst: warp per node (layers 1,2) ----------
__global__ void k_sdot(const float* __restrict__ asrc, const float* __restrict__ adst) {
    __shared__ float sa[HC], sd[HC];
    int t = threadIdx.x;
    if (t < HC) { sa[t] = asrc[t]; sd[t] = adst[t]; }
    __syncthreads();
    int warp = t >> 5, lane = t & 31;
    int n = blockIdx.x * 8 + warp;
    if (n >= NN) return;
    float4 hv = ((const float4*)g_h)[n * 32 + lane];
    float4 a = ((const float4*)sa)[lane];
    float4 d = ((const float4*)sd)[lane];
    float ps = hv.x * a.x + hv.y * a.y + hv.z * a.z + hv.w * a.w;
    float pd = hv.x * d.x + hv.y * d.y + hv.z * d.z + hv.w * d.w;
    for (int off = 4; off; off >>= 1) {
        ps += __shfl_xor_sync(0xffffffffu, ps, off);
        pd += __shfl_xor_sync(0xffffffffu, pd, off);
    }
    if ((lane & 7) == 0) {
        int h = lane >> 3;
        g_ssrc[n * HH + h] = ps;
        g_sdst[n * HH + h] = pd;
    }
}

// ---------- aggregation: warp per dst node, branch-free online softmax ----------
// lane = hd*8 + q : lane covers channels [hd*32 + q*4, +4) => row offset lane*4
__global__ void __launch_bounds__(256) k_agg(const float* __restrict__ bias,
                                             const float* __restrict__ xprev,
                                             float* __restrict__ xout, int layer) {
    __shared__ float sser[(NRELS + 1) * HH];
    int t = threadIdx.x;
    if (t < (NRELS + 1) * HH) sser[t] = g_serel[layer * (NRELS + 1) * HH + t];
    __syncthreads();
    int warp = t >> 5, lane = t & 31;
    int n = blockIdx.x * 8 + warp;
    if (n >= NN) return;
    int hd = lane >> 3;
    int beg = g_rowstart[n], end = g_rowstart[n + 1];
    float sdv = g_sdst[n * HH + hd];
    float m = -1e30f, dsum = 0.f;
    float4 acc = make_float4(0.f, 0.f, 0.f, 0.f);
    const float4* h4 = (const float4*)g_h;

    unsigned pk = g_edgep[beg];
    float ss = g_ssrc[(pk & 0xFFFFu) * HH + hd];
    for (int e = beg; e < end; e++) {
        unsigned cpk = pk; float css = ss;
        if (e + 1 < end) {
            pk = g_edgep[e + 1];
            ss = g_ssrc[(pk & 0xFFFFu) * HH + hd];
        }
        int src = (int)(cpk & 0xFFFFu);
        int typ = (int)(cpk >> 16);
        float a = css + sdv + sser[typ * HH + hd];
        a = (a > 0.f) ? a : 0.2f * a;                  // leaky_relu
        float nm = fmaxf(m, a);
        float sc = __expf(m - nm);                     // 1 if no new max; 0 on first edge
        float w  = __expf(a - nm);
        m = nm;
        float4 v = h4[src * 32 + lane];                // fully coalesced 512B warp load
        dsum = dsum * sc + w;
        acc.x = acc.x * sc + w * v.x;
        acc.y = acc.y * sc + w * v.y;
        acc.z = acc.z * sc + w * v.z;
        acc.w = acc.w * sc + w * v.w;
    }
    float inv = 1.f / (dsum + 1e-16f);
    float4 b4 = ((const float4*)bias)[lane];
    float4 o = make_float4(acc.x * inv + b4.x, acc.y * inv + b4.y,
                           acc.z * inv + b4.z, acc.w * inv + b4.w);
    if (layer > 0) {
        float4 xp = ((const float4*)xprev)[n * 32 + lane];
        o.x += xp.x; o.y += xp.y; o.z += xp.z; o.w += xp.w;
    }
    o.x = fmaxf(o.x, 0.f); o.y = fmaxf(o.y, 0.f);
    o.z = fmaxf(o.z, 0.f); o.w = fmaxf(o.w, 0.f);
    ((float4*)xout)[n * 32 + lane] = o;
}

// ---------- f32x2 SGEMM: C[M,128] = A[M,128] * B[128,128] ----------
__global__ void __launch_bounds__(256) k_gemm(const float* __restrict__ A,
                                              const float* __restrict__ B,
                                              float* __restrict__ Co, int M) {
    __shared__ float As[16][HC];
    __shared__ float Bs[16][HC];
    int t = threadIdx.x;
    int tx = t & 15, ty = t >> 4;
    int row0 = blockIdx.x * 128;
    ull acc2[8][4];
#pragma unroll
    for (int i = 0; i < 8; i++)
#pragma unroll
        for (int j = 0; j < 4; j++) acc2[i][j] = 0ull;

    for (int kc = 0; kc < 128; kc += 16) {
#pragma unroll
        for (int i = 0; i < 2; i++) {
            int f = t * 2 + i;
            int r = f >> 2;
            int kq = (f & 3) << 2;
            float4 v = make_float4(0, 0, 0, 0);
            int gr = row0 + r;
            if (gr < M) v = *(const float4*)(A + gr * 128 + kc + kq);
            As[kq + 0][r] = v.x; As[kq + 1][r] = v.y;
            As[kq + 2][r] = v.z; As[kq + 3][r] = v.w;
        }
#pragma unroll
        for (int i = 0; i < 2; i++) {
            int f = t * 2 + i;
            int k = f >> 5;
            int cq = (f & 31) << 2;
            float4 v = *(const float4*)(B + (kc + k) * 128 + cq);
            Bs[k][cq + 0] = v.x; Bs[k][cq + 1] = v.y;
            Bs[k][cq + 2] = v.z; Bs[k][cq + 3] = v.w;
        }
        __syncthreads();
#pragma unroll
        for (int k = 0; k < 16; k++) {
            float4 a0 = *(const float4*)&As[k][ty * 8];
            float4 a1 = *(const float4*)&As[k][ty * 8 + 4];
            float4 b0 = *(const float4*)&Bs[k][tx * 8];
            float4 b1 = *(const float4*)&Bs[k][tx * 8 + 4];
            ull bb[4] = { pack2(b0.x, b0.y), pack2(b0.z, b0.w),
                          pack2(b1.x, b1.y), pack2(b1.z, b1.w) };
            float avs[8] = { a0.x, a0.y, a0.z, a0.w, a1.x, a1.y, a1.z, a1.w };
#pragma unroll
            for (int i = 0; i < 8; i++) {
                ull aa = pack2(avs[i], avs[i]);
#pragma unroll
                for (int j = 0; j < 4; j++) ffma2(acc2[i][j], aa, bb[j]);
            }
        }
        __syncthreads();
    }
#pragma unroll
    for (int i = 0; i < 8; i++) {
        int gr = row0 + ty * 8 + i;
        if (gr >= M) continue;
#pragma unroll
        for (int j = 0; j < 4; j++) {
            *(float2*)&Co[gr * 128 + tx * 8 + 2 * j] =
                make_float2(lo2(acc2[i][j]), hi2(acc2[i][j]));
        }
    }
}

// ---------- fused MLP head: out = sigmoid(relu(A@W1+b1)@W2 + b2) ----------
__global__ void __launch_bounds__(256) k_mlp(const float* __restrict__ A,
                                             const float* __restrict__ W1,
                                             const float* __restrict__ b1,
                                             const float* __restrict__ W2,
                                             const float* __restrict__ b2,
                                             float* __restrict__ out, int M) {
    __shared__ float As[16][HC];
    __shared__ float Bs[16][HC];
    __shared__ float sred[128][17];
    __shared__ float sw2[HC];
    __shared__ float sb1[HC];
    int t = threadIdx.x;
    int tx = t & 15, ty = t >> 4;
    int row0 = blockIdx.x * 128;
    if (t < HC) {
        sw2[t] = (t < HID) ? W2[t] : 0.f;
        sb1[t] = (t < HID) ? b1[t] : 0.f;
    }
    ull acc2[8][4];
#pragma unroll
    for (int i = 0; i < 8; i++)
#pragma unroll
        for (int j = 0; j < 4; j++) acc2[i][j] = 0ull;

    for (int kc = 0; kc < 128; kc += 16) {
#pragma unroll
        for (int i = 0; i < 2; i++) {
            int f = t * 2 + i;
            int r = f >> 2;
            int kq = (f & 3) << 2;
            float4 v = make_float4(0, 0, 0, 0);
            int gr = row0 + r;
            if (gr < M) v = *(const float4*)(A + gr * 128 + kc + kq);
            As[kq + 0][r] = v.x; As[kq + 1][r] = v.y;
            As[kq + 2][r] = v.z; As[kq + 3][r] = v.w;
        }
#pragma unroll
        for (int i = 0; i < 2; i++) {
            int f = t * 2 + i;
            int k = f >> 5;
            int cq = (f & 31) << 2;
            float4 v = make_float4(0, 0, 0, 0);
            if (cq < HID) v = *(const float4*)(W1 + (kc + k) * HID + cq);
            Bs[k][cq + 0] = v.x; Bs[k][cq + 1] = v.y;
            Bs[k][cq + 2] = v.z; Bs[k][cq + 3] = v.w;
        }
        __syncthreads();
#pragma unroll
        for (int k = 0; k < 16; k++) {
            float4 a0 = *(const float4*)&As[k][ty * 8];
            float4 a1 = *(const float4*)&As[k][ty * 8 + 4];
            float4 b0 = *(const float4*)&Bs[k][tx * 8];
            float4 b1v = *(const float4*)&Bs[k][tx * 8 + 4];
            ull bb[4] = { pack2(b0.x, b0.y), pack2(b0.z, b0.w),
                          pack2(b1v.x, b1v.y), pack2(b1v.z, b1v.w) };
            float avs[8] = { a0.x, a0.y, a0.z, a0.w, a1.x, a1.y, a1.z, a1.w };
#pragma unroll
            for (int i = 0; i < 8; i++) {
                ull aa = pack2(avs[i], avs[i]);
#pragma unroll
                for (int j = 0; j < 4; j++) ffma2(acc2[i][j], aa, bb[j]);
            }
        }
        __syncthreads();
    }
    // epilogue: relu(+b1) then dot with W2, reduce across 16 tx threads
#pragma unroll
    for (int i = 0; i < 8; i++) {
        float p = 0.f;
#pragma unroll
        for (int j = 0; j < 4; j++) {
            int gc = tx * 8 + 2 * j;
            float v0 = fmaxf(lo2(acc2[i][j]) + sb1[gc], 0.f);
            float v1 = fmaxf(hi2(acc2[i][j]) + sb1[gc + 1], 0.f);
            p += v0 * sw2[gc] + v1 * sw2[gc + 1];
        }
        sred[ty * 8 + i][tx] = p;
    }
    __syncthreads();
    if (t < 128) {
        int gr = row0 + t;
        if (gr < M) {
            float s = 0.f;
#pragma unroll
            for (int j = 0; j < 16; j++) s += sred[t][j];
            out[gr] = 1.f / (1.f + __expf(-(s + b2[0])));
        }
    }
}

// ---------- host ----------
extern "C" void kernel_launch(void* const* d_in, const int* in_sizes, int n_in,
                              void* d_out, int out_size) {
    const float* x     = (const float*)d_in[0];
    const int*   ei    = (const int*)d_in[1];
    const int*   et    = (const int*)d_in[2];
    const float* eemb  = (const float*)d_in[3];
    const float* W0    = (const float*)d_in[4];
    const float* W1    = (const float*)d_in[5];
    const float* W2    = (const float*)d_in[6];
    const float* attS  = (const float*)d_in[7];
    const float* attD  = (const float*)d_in[8];
    const float* attE  = (const float*)d_in[9];
    const float* Wedge = (const float*)d_in[10];
    const float* bias  = (const float*)d_in[11];
    const float* mW1   = (const float*)d_in[12];
    const float* mb1   = (const float*)d_in[13];
    const float* mW2   = (const float*)d_in[14];
    const float* mb2   = (const float*)d_in[15];
    float* out = (float*)d_out;

    float *ph, *pxA, *pxB;
    cudaGetSymbolAddress((void**)&ph, g_h);
    cudaGetSymbolAddress((void**)&pxA, g_xA);
    cudaGetSymbolAddress((void**)&pxB, g_xB);

    // graph build (reused by all 3 layers)
    k_init<<<(NN + 255) / 256, 256>>>();
    k_histcount<<<(EE + 255) / 256, 256>>>(ei, et);
    k_scan<<<1, 1024>>>();
    k_scatter<<<(EP + 255) / 256, 256>>>(ei, et);
    k_pre<<<1, 256>>>(W0, Wedge, attE, eemb, attS, attD);

    int gAgg = (NN + 7) / 8;
    int gSd  = (NN + 7) / 8;
    int gGm  = (NN + 127) / 128;

    // layer 0 (rank-1 projection + fused sdot, no residual)
    k_h0<<<(NN * 32 + 255) / 256, 256>>>(x);
    k_agg<<<gAgg, 256>>>(bias + 0 * HC, nullptr, pxA, 0);

    // layer 1
    k_gemm<<<gGm, 256>>>(pxA, W1, ph, NN);
    k_sdot<<<gSd, 256>>>(attS + 1 * HC, attD + 1 * HC);
    k_agg<<<gAgg, 256>>>(bias + 1 * HC, pxA, pxB, 1);

    // layer 2
    k_gemm<<<gGm, 256>>>(pxB, W2, ph, NN);
    k_sdot<<<gSd, 256>>>(attS + 2 * HC, attD + 2 * HC);
    k_agg<<<gAgg, 256>>>(bias + 2 * HC, pxB, pxA, 2);

    // fused MLP head
    k_mlp<<<gGm, 256>>>(pxA, mW1, mb1, mW2, mb2, out, NN);
}

// round 4
// speedup vs baseline: 1.7976x; 1.1379x over previous
#include <cuda_runtime.h>
#include <cuda_fp16.h>

#define NN 50000
#define EE 800000
#define EP (EE + NN)
#define HH 4
#define CC 32
#define HC 128
#define EDIM 8
#define NRELS 16
#define NLAYERS 3
#define HID 100

typedef unsigned long long ull;

// ---------- scratch (device globals: no allocation allowed) ----------
__device__ __half g_hh[NN * HC];        // projected features (fp16, message table)
__device__ float g_xA[NN * HC];         // ping
__device__ float g_xB[NN * HC];         // pong
__device__ float g_ssrc[NN * HH];
__device__ float g_sdst[NN * HH];
__device__ int   g_rowstart[NN + 1];
__device__ int   g_counts[NN];
__device__ int   g_cursor[NN];
__device__ unsigned g_edgep[EP];        // src | (type<<16), sorted by dst
__device__ float g_serel[NLAYERS * (NRELS + 1) * HH];
__device__ float g_w0sum[HC];
__device__ float g_k0[8];               // layer0 rank-1 att dots (src 0..3, dst 4..7)
__device__ int   g_hist[NRELS];

// ---------- f32x2 helpers ----------
__device__ __forceinline__ void ffma2(ull &d, ull a, ull b) {
    asm("fma.rn.f32x2 %0, %1, %2, %3;" : "=l"(d) : "l"(a), "l"(b), "l"(d));
}
__device__ __forceinline__ ull pack2(float x, float y) {
    ull r; asm("mov.b64 %0, {%1, %2};" : "=l"(r) : "f"(x), "f"(y)); return r;
}
__device__ __forceinline__ float lo2(ull v) { return __uint_as_float((unsigned)v); }
__device__ __forceinline__ float hi2(ull v) { return __uint_as_float((unsigned)(v >> 32)); }

// ---------- build: counts + type histogram ----------
__global__ void k_init() {
    int i = blockIdx.x * blockDim.x + threadIdx.x;
    if (i < NN) g_counts[i] = 1;          // self-loop
    if (i < NRELS) g_hist[i] = 0;
}

__global__ void k_histcount(const int* __restrict__ ei, const int* __restrict__ et) {
    __shared__ int sh[NRELS];
    if (threadIdx.x < NRELS) sh[threadIdx.x] = 0;
    __syncthreads();
    int i = blockIdx.x * blockDim.x + threadIdx.x;
    if (i < EE) {
        atomicAdd(&g_counts[ei[EE + i]], 1);
        atomicAdd(&sh[et[i]], 1);
    }
    __syncthreads();
    if (threadIdx.x < NRELS) atomicAdd(&g_hist[threadIdx.x], sh[threadIdx.x]);
}

// ---------- exclusive scan (1 block, hierarchical) ----------
__global__ void k_scan() {
    __shared__ int ss[1024];
    const int CH = (NN + 1023) / 1024;
    int t = threadIdx.x;
    int beg = t * CH;
    int end = min(beg + CH, NN);
    int s = 0;
    for (int i = beg; i < end; i++) s += g_counts[i];
    ss[t] = s;
    __syncthreads();
    for (int off = 1; off < 1024; off <<= 1) {
        int v = 0;
        if (t >= off) v = ss[t - off];
        __syncthreads();
        ss[t] += v;
        __syncthreads();
    }
    int run = (t == 0) ? 0 : ss[t - 1];
    for (int i = beg; i < end; i++) {
        g_rowstart[i] = run;
        g_cursor[i]   = run;
        run += g_counts[i];
    }
    if (t == 0) g_rowstart[NN] = EP;
}

// ---------- scatter edges into dst-CSR (packed: src | type<<16) ----------
__global__ void k_scatter(const int* __restrict__ ei, const int* __restrict__ et) {
    int i = blockIdx.x * blockDim.x + threadIdx.x;
    if (i < EE) {
        int d = ei[EE + i];
        int p = atomicAdd(&g_cursor[d], 1);
        g_edgep[p] = (unsigned)ei[i] | ((unsigned)et[i] << 16);
    } else if (i < EP) {
        int n = i - EE;
        int p = atomicAdd(&g_cursor[n], 1);
        g_edgep[p] = (unsigned)n | ((unsigned)NRELS << 16);   // self-loop sentinel
    }
}

// ---------- tiny precompute: w0sum + per-relation edge scores + layer0 att dots ----------
__global__ void k_pre(const float* __restrict__ W0, const float* __restrict__ Wedge,
                      const float* __restrict__ attE, const float* __restrict__ eemb,
                      const float* __restrict__ attS, const float* __restrict__ attD) {
    int t = threadIdx.x;
    if (t < HC) {
        float s = 0.f;
        for (int c = 0; c < CC; c++) s += W0[c * HC + t];
        g_w0sum[t] = s;
    }
    if (t < NLAYERS * (NRELS + 1) * HH) {
        int l = t / ((NRELS + 1) * HH);
        int rem = t % ((NRELS + 1) * HH);
        int r = rem / HH;
        int h = rem % HH;
        float s = 0.f;
        for (int d = 0; d < EDIM; d++) {
            float u = 0.f;
            for (int c = 0; c < CC; c++)
                u += Wedge[(l * EDIM + d) * HC + h * CC + c] * attE[l * HC + h * CC + c];
            float ea;
            if (r < NRELS) {
                ea = eemb[r * EDIM + d];
            } else {
                float f = 0.f;
                for (int rr = 0; rr < NRELS; rr++)
                    f += (float)g_hist[rr] * eemb[rr * EDIM + d];
                ea = f / (float)EE;
            }
            s += ea * u;
        }
        g_serel[t] = s;
    }
    __syncthreads();
    if (t < 8) {                    // layer-0 rank-1 attention dots
        int h = t & 3;
        const float* av = (t < 4) ? attS : attD;   // layer0 slice
        float s = 0.f;
        for (int c = 0; c < CC; c++) s += g_w0sum[h * CC + c] * av[h * CC + c];
        g_k0[t] = s;
    }
}

// ---------- layer-0 aggregation: fully rank-1, scalar online softmax ----------
// warp per dst node; all per-edge state is uniform scalars (x[src]); channels
// expanded only at writeback via w0sum.
__global__ void __launch_bounds__(256) k_agg0(const float* __restrict__ x,
                                              const float* __restrict__ bias,
                                              float* __restrict__ xout) {
    __shared__ float sser[(NRELS + 1) * HH];
    int t = threadIdx.x;
    if (t < (NRELS + 1) * HH) sser[t] = g_serel[t];   // layer 0 slice
    __syncthreads();
    int warp = t >> 5, lane = t & 31;
    int n = blockIdx.x * 8 + warp;
    if (n >= NN) return;
    int hd = lane >> 3;
    float4 w4 = ((const float4*)g_w0sum)[lane];
    float k0s = g_k0[hd];
    int beg = g_rowstart[n], end = g_rowstart[n + 1];
    float sdv = x[n] * g_k0[4 + hd];
    float m = -1e30f, dsum = 0.f, sx = 0.f;

    unsigned pk = g_edgep[beg];
    float xs = x[pk & 0xFFFFu];
    for (int e = beg; e < end; e++) {
        unsigned cpk = pk; float cxs = xs;
        if (e + 1 < end) {
            pk = g_edgep[e + 1];
            xs = x[pk & 0xFFFFu];
        }
        int typ = (int)(cpk >> 16);
        float a = cxs * k0s + sdv + sser[typ * HH + hd];
        a = (a > 0.f) ? a : 0.2f * a;                  // leaky_relu
        float nm = fmaxf(m, a);
        float sc = __expf(m - nm);
        float w  = __expf(a - nm);
        m = nm;
        dsum = dsum * sc + w;
        sx   = sx * sc + w * cxs;
    }
    float s = sx / (dsum + 1e-16f);
    float4 b4 = ((const float4*)bias)[lane];
    float4 o = make_float4(fmaxf(s * w4.x + b4.x, 0.f), fmaxf(s * w4.y + b4.y, 0.f),
                           fmaxf(s * w4.z + b4.z, 0.f), fmaxf(s * w4.w + b4.w, 0.f));
    ((float4*)xout)[n * 32 + lane] = o;
}

// ---------- aggregation layers 1,2: warp per dst node, fp16 message gather ----------
__global__ void __launch_bounds__(256) k_agg(const float* __restrict__ bias,
                                             const float* __restrict__ xprev,
                                             float* __restrict__ xout, int layer) {
    __shared__ float sser[(NRELS + 1) * HH];
    int t = threadIdx.x;
    if (t < (NRELS + 1) * HH) sser[t] = g_serel[layer * (NRELS + 1) * HH + t];
    __syncthreads();
    int warp = t >> 5, lane = t & 31;
    int n = blockIdx.x * 8 + warp;
    if (n >= NN) return;
    int hd = lane >> 3;
    int beg = g_rowstart[n], end = g_rowstart[n + 1];
    float sdv = g_sdst[n * HH + hd];
    float m = -1e30f, dsum = 0.f;
    float4 acc = make_float4(0.f, 0.f, 0.f, 0.f);

    unsigned pk = g_edgep[beg];
    int psrc = (int)(pk & 0xFFFFu);
    float ss = g_ssrc[psrc * HH + hd];
    uint2 rv = ((const uint2*)(g_hh + psrc * HC))[lane];     // 8B/lane, coalesced 256B
    for (int e = beg; e < end; e++) {
        unsigned cpk = pk; float css = ss; uint2 crv = rv;
        if (e + 1 < end) {
            pk = g_edgep[e + 1];
            psrc = (int)(pk & 0xFFFFu);
            ss = g_ssrc[psrc * HH + hd];
            rv = ((const uint2*)(g_hh + psrc * HC))[lane];
        }
        int typ = (int)(cpk >> 16);
        float a = css + sdv + sser[typ * HH + hd];
        a = (a > 0.f) ? a : 0.2f * a;                  // leaky_relu
        float nm = fmaxf(m, a);
        float sc = __expf(m - nm);
        float w  = __expf(a - nm);
        m = nm;
        float2 f0 = __half22float2(*(__half2*)&crv.x);
        float2 f1 = __half22float2(*(__half2*)&crv.y);
        dsum = dsum * sc + w;
        acc.x = acc.x * sc + w * f0.x;
        acc.y = acc.y * sc + w * f0.y;
        acc.z = acc.z * sc + w * f1.x;
        acc.w = acc.w * sc + w * f1.y;
    }
    float inv = 1.f / (dsum + 1e-16f);
    float4 b4 = ((const float4*)bias)[lane];
    float4 xp = ((const float4*)xprev)[n * 32 + lane];
    float4 o = make_float4(acc.x * inv + b4.x + xp.x, acc.y * inv + b4.y + xp.y,
                           acc.z * inv + b4.z + xp.z, acc.w * inv + b4.w + xp.w);
    o.x = fmaxf(o.x, 0.f); o.y = fmaxf(o.y, 0.f);
    o.z = fmaxf(o.z, 0.f); o.w = fmaxf(o.w, 0.f);
    ((float4*)xout)[n * 32 + lane] = o;
}

// ---------- f32x2 SGEMM + fused epilogue: h(fp16), s_src, s_dst ----------
__global__ void __launch_bounds__(256) k_gemm(const float* __restrict__ A,
                                              const float* __restrict__ B,
                                              const float* __restrict__ attS,
                                              const float* __restrict__ attD,
                                              int M) {
    __shared__ float As[16][HC];
    __shared__ float Bs[16][HC];
    __shared__ float sa[HC], sd[HC];
    int t = threadIdx.x;
    int tx = t & 15, ty = t >> 4;
    int row0 = blockIdx.x * 128;
    if (t < HC) { sa[t] = attS[t]; sd[t] = attD[t]; }
    ull acc2[8][4];
#pragma unroll
    for (int i = 0; i < 8; i++)
#pragma unroll
        for (int j = 0; j < 4; j++) acc2[i][j] = 0ull;

    for (int kc = 0; kc < 128; kc += 16) {
#pragma unroll
        for (int i = 0; i < 2; i++) {
            int f = t * 2 + i;
            int r = f >> 2;
            int kq = (f & 3) << 2;
            float4 v = make_float4(0, 0, 0, 0);
            int gr = row0 + r;
            if (gr < M) v = *(const float4*)(A + gr * 128 + kc + kq);
            As[kq + 0][r] = v.x; As[kq + 1][r] = v.y;
            As[kq + 2][r] = v.z; As[kq + 3][r] = v.w;
        }
#pragma unroll
        for (int i = 0; i < 2; i++) {
            int f = t * 2 + i;
            int k = f >> 5;
            int cq = (f & 31) << 2;
            float4 v = *(const float4*)(B + (kc + k) * 128 + cq);
            Bs[k][cq + 0] = v.x; Bs[k][cq + 1] = v.y;
            Bs[k][cq + 2] = v.z; Bs[k][cq + 3] = v.w;
        }
        __syncthreads();
#pragma unroll
        for (int k = 0; k < 16; k++) {
            float4 a0 = *(const float4*)&As[k][ty * 8];
            float4 a1 = *(const float4*)&As[k][ty * 8 + 4];
            float4 b0 = *(const float4*)&Bs[k][tx * 8];
            float4 b1 = *(const float4*)&Bs[k][tx * 8 + 4];
            ull bb[4] = { pack2(b0.x, b0.y), pack2(b0.z, b0.w),
                          pack2(b1.x, b1.y), pack2(b1.z, b1.w) };
            float avs[8] = { a0.x, a0.y, a0.z, a0.w, a1.x, a1.y, a1.z, a1.w };
#pragma unroll
            for (int i = 0; i < 8; i++) {
                ull aa = pack2(avs[i], avs[i]);
#pragma unroll
                for (int j = 0; j < 4; j++) ffma2(acc2[i][j], aa, bb[j]);
            }
        }
        __syncthreads();
    }
    // epilogue: fp16 h store + fused s_src/s_dst (quad-shuffle over tx%4)
    int hd = tx >> 2;
#pragma unroll
    for (int i = 0; i < 8; i++) {
        int gr = row0 + ty * 8 + i;
        float f[8];
#pragma unroll
        for (int j = 0; j < 4; j++) { f[2 * j] = lo2(acc2[i][j]); f[2 * j + 1] = hi2(acc2[i][j]); }
        float ps = 0.f, pd = 0.f;
#pragma unroll
        for (int j = 0; j < 8; j++) {
            ps += f[j] * sa[tx * 8 + j];
            pd += f[j] * sd[tx * 8 + j];
        }
        ps += __shfl_xor_sync(0xffffffffu, ps, 1);
        pd += __shfl_xor_sync(0xffffffffu, pd, 1);
        ps += __shfl_xor_sync(0xffffffffu, ps, 2);
        pd += __shfl_xor_sync(0xffffffffu, pd, 2);
        if (gr < M) {
            __half2 h0 = __floats2half2_rn(f[0], f[1]);
            __half2 h1 = __floats2half2_rn(f[2], f[3]);
            __half2 h2 = __floats2half2_rn(f[4], f[5]);
            __half2 h3 = __floats2half2_rn(f[6], f[7]);
            uint4 u = make_uint4(*(unsigned*)&h0, *(unsigned*)&h1,
                                 *(unsigned*)&h2, *(unsigned*)&h3);
            *(uint4*)(g_hh + gr * HC + tx * 8) = u;
            if ((tx & 3) == 0) {
                g_ssrc[gr * HH + hd] = ps;
                g_sdst[gr * HH + hd] = pd;
            }
        }
    }
}

// ---------- fused MLP head: out = sigmoid(relu(A@W1+b1)@W2 + b2) ----------
__global__ void __launch_bounds__(256) k_mlp(const float* __restrict__ A,
                                             const float* __restrict__ W1,
                                             const float* __restrict__ b1,
                                             const float* __restrict__ W2,
                                             const float* __restrict__ b2,
                                             float* __restrict__ out, int M) {
    __shared__ float As[16][HC];
    __shared__ float Bs[16][HC];
    __shared__ float sred[128][17];
    __shared__ float sw2[HC];
    __shared__ float sb1[HC];
    int t = threadIdx.x;
    int tx = t & 15, ty = t >> 4;
    int row0 = blockIdx.x * 128;
    if (t < HC) {
        sw2[t] = (t < HID) ? W2[t] : 0.f;
        sb1[t] = (t < HID) ? b1[t] : 0.f;
    }
    ull acc2[8][4];
#pragma unroll
    for (int i = 0; i < 8; i++)
#pragma unroll
        for (int j = 0; j < 4; j++) acc2[i][j] = 0ull;

    for (int kc = 0; kc < 128; kc += 16) {
#pragma unroll
        for (int i = 0; i < 2; i++) {
            int f = t * 2 + i;
            int r = f >> 2;
            int kq = (f & 3) << 2;
            float4 v = make_float4(0, 0, 0, 0);
            int gr = row0 + r;
            if (gr < M) v = *(const float4*)(A + gr * 128 + kc + kq);
            As[kq + 0][r] = v.x; As[kq + 1][r] = v.y;
            As[kq + 2][r] = v.z; As[kq + 3][r] = v.w;
        }
#pragma unroll
        for (int i = 0; i < 2; i++) {
            int f = t * 2 + i;
            int k = f >> 5;
            int cq = (f & 31) << 2;
            float4 v = make_float4(0, 0, 0, 0);
            if (cq < HID) v = *(const float4*)(W1 + (kc + k) * HID + cq);
            Bs[k][cq + 0] = v.x; Bs[k][cq + 1] = v.y;
            Bs[k][cq + 2] = v.z; Bs[k][cq + 3] = v.w;
        }
        __syncthreads();
#pragma unroll
        for (int k = 0; k < 16; k++) {
            float4 a0 = *(const float4*)&As[k][ty * 8];
            float4 a1 = *(const float4*)&As[k][ty * 8 + 4];
            float4 b0 = *(const float4*)&Bs[k][tx * 8];
            float4 b1v = *(const float4*)&Bs[k][tx * 8 + 4];
            ull bb[4] = { pack2(b0.x, b0.y), pack2(b0.z, b0.w),
                          pack2(b1v.x, b1v.y), pack2(b1v.z, b1v.w) };
            float avs[8] = { a0.x, a0.y, a0.z, a0.w, a1.x, a1.y, a1.z, a1.w };
#pragma unroll
            for (int i = 0; i < 8; i++) {
                ull aa = pack2(avs[i], avs[i]);
#pragma unroll
                for (int j = 0; j < 4; j++) ffma2(acc2[i][j], aa, bb[j]);
            }
        }
        __syncthreads();
    }
    // epilogue: relu(+b1) then dot with W2, reduce across 16 tx threads
#pragma unroll
    for (int i = 0; i < 8; i++) {
        float p = 0.f;
#pragma unroll
        for (int j = 0; j < 4; j++) {
            int gc = tx * 8 + 2 * j;
            float v0 = fmaxf(lo2(acc2[i][j]) + sb1[gc], 0.f);
            float v1 = fmaxf(hi2(acc2[i][j]) + sb1[gc + 1], 0.f);
            p += v0 * sw2[gc] + v1 * sw2[gc + 1];
        }
        sred[ty * 8 + i][tx] = p;
    }
    __syncthreads();
    if (t < 128) {
        int gr = row0 + t;
        if (gr < M) {
            float s = 0.f;
#pragma unroll
            for (int j = 0; j < 16; j++) s += sred[t][j];
            out[gr] = 1.f / (1.f + __expf(-(s + b2[0])));
        }
    }
}

// ---------- host ----------
extern "C" void kernel_launch(void* const* d_in, const int* in_sizes, int n_in,
                              void* d_out, int out_size) {
    const float* x     = (const float*)d_in[0];
    const int*   ei    = (const int*)d_in[1];
    const int*   et    = (const int*)d_in[2];
    const float* eemb  = (const float*)d_in[3];
    const float* W0    = (const float*)d_in[4];
    const float* W1    = (const float*)d_in[5];
    const float* W2    = (const float*)d_in[6];
    const float* attS  = (const float*)d_in[7];
    const float* attD  = (const float*)d_in[8];
    const float* attE  = (const float*)d_in[9];
    const float* Wedge = (const float*)d_in[10];
    const float* bias  = (const float*)d_in[11];
    const float* mW1   = (const float*)d_in[12];
    const float* mb1   = (const float*)d_in[13];
    const float* mW2   = (const float*)d_in[14];
    const float* mb2   = (const float*)d_in[15];
    float* out = (float*)d_out;

    float *pxA, *pxB;
    cudaGetSymbolAddress((void**)&pxA, g_xA);
    cudaGetSymbolAddress((void**)&pxB, g_xB);

    // graph build (reused by all 3 layers)
    k_init<<<(NN + 255) / 256, 256>>>();
    k_histcount<<<(EE + 255) / 256, 256>>>(ei, et);
    k_scan<<<1, 1024>>>();
    k_scatter<<<(EP + 255) / 256, 256>>>(ei, et);
    k_pre<<<1, 256>>>(W0, Wedge, attE, eemb, attS, attD);

    int gAgg = (NN + 7) / 8;
    int gGm  = (NN + 127) / 128;

    // layer 0: fully rank-1 aggregation (no h materialization at all)
    k_agg0<<<gAgg, 256>>>(x, bias + 0 * HC, pxA);

    // layer 1
    k_gemm<<<gGm, 256>>>(pxA, W1, attS + 1 * HC, attD + 1 * HC, NN);
    k_agg<<<gAgg, 256>>>(bias + 1 * HC, pxA, pxB, 1);

    // layer 2
    k_gemm<<<gGm, 256>>>(pxB, W2, attS + 2 * HC, attD + 2 * HC, NN);
    k_agg<<<gAgg, 256>>>(bias + 2 * HC, pxB, pxA, 2);

    // fused MLP head
    k_mlp<<<gGm, 256>>>(pxA, mW1, mb1, mW2, mb2, out, NN);
}